// round 5
// baseline (speedup 1.0000x reference)
#include <cuda_runtime.h>
#include <cuda_bf16.h>
#include <cstdint>

#define N_NODES 50000
#define N_EDGES 1600000
#define FEAT    48
#define NUM_RELS 8

// ---------------------------------------------------------------------------
// Scratch (__device__ globals — no allocations):
//   g_h2   : h2[n][r][48]              76.8 MB (L2-resident working set)
//   g_cnt  : per-dst edge counts        200 KB
//   g_off  : exclusive offsets (+total) 200 KB
//   g_cur  : scatter cursors            200 KB
//   g_meta : sorted {row_offset, norm}  12.8 MB
// ---------------------------------------------------------------------------
__device__ float g_h2[(size_t)N_NODES * NUM_RELS * FEAT];
__device__ int   g_cnt[N_NODES];
__device__ int   g_off[N_NODES + 1];
__device__ int   g_cur[N_NODES];
__device__ int2  g_meta[N_EDGES];
__device__ int   g_src_is64;

// ---------------------------------------------------------------------------
// Packed f32x2 helpers (Blackwell) — ptxas never auto-fuses these from C++.
// ---------------------------------------------------------------------------
__device__ __forceinline__ unsigned long long pack2(float lo, float hi) {
    unsigned long long r;
    asm("mov.b64 %0, {%1, %2};" : "=l"(r) : "f"(lo), "f"(hi));
    return r;
}
__device__ __forceinline__ void unpack2(float& lo, float& hi, unsigned long long v) {
    asm("mov.b64 {%0, %1}, %2;" : "=f"(lo), "=f"(hi) : "l"(v));
}
#define FMA2(d, a, b) \
    asm("fma.rn.f32x2 %0, %1, %2, %0;" : "+l"(d) : "l"(a), "l"(b))

// ---------------------------------------------------------------------------
// src dtype detection (int64 vs int32): hi words of 256 int64s all zero
// cannot happen by chance for random node ids.
// ---------------------------------------------------------------------------
__global__ void detect_kernel(const int* __restrict__ src) {
    __shared__ int s_any;
    if (threadIdx.x == 0) s_any = 0;
    __syncthreads();
    unsigned v = (unsigned)src[2 * threadIdx.x + 1];
    unsigned any = __ballot_sync(0xFFFFFFFFu, v != 0u);
    if ((threadIdx.x & 31) == 0 && any) atomicOr(&s_any, 1);
    __syncthreads();
    if (threadIdx.x == 0) g_src_is64 = (s_any == 0) ? 1 : 0;
}

// ---------------------------------------------------------------------------
// K1: fused dense stage, 2 nodes per thread.
//   h1 = relu(x @ W1[r] + b1); h2 = h1 @ W2[r]  -> g_h2[n][r][:]
// 128 threads / block -> 256 nodes, one relation (blockIdx.y).
// Stage-1 weight LDS amortized over both nodes (breaks LDS/FMA saturation tie).
// Stage-2 runs per-node sequentially to cap register pressure (~160 regs).
// ---------------------------------------------------------------------------
__global__ __launch_bounds__(128, 2)
void rgcn_gemm_kernel(const float* __restrict__ X,
                      const float* __restrict__ W1,
                      const float* __restrict__ W2,
                      const float* __restrict__ b1) {
    __shared__ __align__(16) float W1s[FEAT * FEAT];
    __shared__ __align__(16) float W2s[FEAT * FEAT];
    __shared__ float b1s[FEAT];

    const int r   = blockIdx.y;
    const int tid = threadIdx.x;

    const float* w1g = W1 + (size_t)r * FEAT * FEAT;
    const float* w2g = W2 + (size_t)r * FEAT * FEAT;
    for (int k = tid; k < FEAT * FEAT; k += 128) {
        W1s[k] = w1g[k];
        W2s[k] = w2g[k];
    }
    if (tid < FEAT) b1s[tid] = b1[tid];
    __syncthreads();

    const int n0 = blockIdx.x * 256 + tid;
    const int n1 = n0 + 128;
    const bool v0 = (n0 < N_NODES);
    const bool v1 = (n1 < N_NODES);
    const int c0 = v0 ? n0 : 0;  // clamped: harmless loads, guarded stores
    const int c1 = v1 ? n1 : 0;

    // ---- stage 1 (both nodes share weight loads) ----
    unsigned long long accA[FEAT / 2], accB[FEAT / 2];
#pragma unroll
    for (int k = 0; k < FEAT / 2; k++) {
        unsigned long long b = pack2(b1s[2 * k], b1s[2 * k + 1]);
        accA[k] = b;
        accB[k] = b;
    }

    const float4* xa4 = reinterpret_cast<const float4*>(X + (size_t)c0 * FEAT);
    const float4* xb4 = reinterpret_cast<const float4*>(X + (size_t)c1 * FEAT);
#pragma unroll
    for (int i4 = 0; i4 < FEAT / 4; i4++) {
        float4 xa = xa4[i4];
        float4 xb = xb4[i4];
#pragma unroll
        for (int u = 0; u < 4; u++) {
            float ai = (u == 0) ? xa.x : (u == 1) ? xa.y : (u == 2) ? xa.z : xa.w;
            float bi = (u == 0) ? xb.x : (u == 1) ? xb.y : (u == 2) ? xb.z : xb.w;
            unsigned long long a2 = pack2(ai, ai);
            unsigned long long b2 = pack2(bi, bi);
            const ulonglong2* w =
                reinterpret_cast<const ulonglong2*>(W1s + (i4 * 4 + u) * FEAT);
#pragma unroll
            for (int k = 0; k < FEAT / 4; k++) {
                ulonglong2 wv = w[k];
                FMA2(accA[2 * k],     a2, wv.x);
                FMA2(accA[2 * k + 1], a2, wv.y);
                FMA2(accB[2 * k],     b2, wv.x);
                FMA2(accB[2 * k + 1], b2, wv.y);
            }
        }
    }

    float hA[FEAT], hB[FEAT];
#pragma unroll
    for (int k = 0; k < FEAT / 2; k++) {
        float lo, hi;
        unpack2(lo, hi, accA[k]);
        hA[2 * k]     = fmaxf(lo, 0.0f);
        hA[2 * k + 1] = fmaxf(hi, 0.0f);
        unpack2(lo, hi, accB[k]);
        hB[2 * k]     = fmaxf(lo, 0.0f);
        hB[2 * k + 1] = fmaxf(hi, 0.0f);
    }

    // ---- stage 2, node A ----
    {
        unsigned long long acc2[FEAT / 2];
#pragma unroll
        for (int k = 0; k < FEAT / 2; k++) acc2[k] = 0ull;
#pragma unroll
        for (int j = 0; j < FEAT; j++) {
            unsigned long long hj = pack2(hA[j], hA[j]);
            const ulonglong2* w = reinterpret_cast<const ulonglong2*>(W2s + j * FEAT);
#pragma unroll
            for (int k = 0; k < FEAT / 4; k++) {
                ulonglong2 wv = w[k];
                FMA2(acc2[2 * k],     hj, wv.x);
                FMA2(acc2[2 * k + 1], hj, wv.y);
            }
        }
        if (v0) {
            ulonglong2* orow = reinterpret_cast<ulonglong2*>(
                g_h2 + ((size_t)n0 * NUM_RELS + r) * FEAT);
#pragma unroll
            for (int k = 0; k < FEAT / 4; k++) {
                ulonglong2 o; o.x = acc2[2 * k]; o.y = acc2[2 * k + 1];
                orow[k] = o;
            }
        }
    }

    // ---- stage 2, node B ----
    {
        unsigned long long acc2[FEAT / 2];
#pragma unroll
        for (int k = 0; k < FEAT / 2; k++) acc2[k] = 0ull;
#pragma unroll
        for (int j = 0; j < FEAT; j++) {
            unsigned long long hj = pack2(hB[j], hB[j]);
            const ulonglong2* w = reinterpret_cast<const ulonglong2*>(W2s + j * FEAT);
#pragma unroll
            for (int k = 0; k < FEAT / 4; k++) {
                ulonglong2 wv = w[k];
                FMA2(acc2[2 * k],     hj, wv.x);
                FMA2(acc2[2 * k + 1], hj, wv.y);
            }
        }
        if (v1) {
            ulonglong2* orow = reinterpret_cast<ulonglong2*>(
                g_h2 + ((size_t)n1 * NUM_RELS + r) * FEAT);
#pragma unroll
            for (int k = 0; k < FEAT / 4; k++) {
                ulonglong2 o; o.x = acc2[2 * k]; o.y = acc2[2 * k + 1];
                orow[k] = o;
            }
        }
    }
}

// ---------------------------------------------------------------------------
// K2a: zero per-dst counts.
// ---------------------------------------------------------------------------
__global__ void zero_cnt_kernel() {
    int i = blockIdx.x * 256 + threadIdx.x;
    if (i < N_NODES) g_cnt[i] = 0;
}

// ---------------------------------------------------------------------------
// K2b: histogram of dst (int atomics — cheap vs float RED).
// ---------------------------------------------------------------------------
__global__ __launch_bounds__(256)
void hist_kernel(const int* __restrict__ dst) {
    int e = blockIdx.x * 256 + threadIdx.x;
    if (e < N_EDGES) atomicAdd(&g_cnt[dst[e]], 1);
}

// ---------------------------------------------------------------------------
// K2c: single-block exclusive scan of g_cnt -> g_off, g_cur.
// ---------------------------------------------------------------------------
__global__ __launch_bounds__(1024)
void scan_kernel() {
    __shared__ int partial[1024];
    const int t = threadIdx.x;
    const int CH = (N_NODES + 1023) / 1024;  // 49
    const int base = t * CH;

    int s = 0;
    for (int i = 0; i < CH; i++) {
        int idx = base + i;
        if (idx < N_NODES) s += g_cnt[idx];
    }
    partial[t] = s;
    __syncthreads();
    for (int o = 1; o < 1024; o <<= 1) {
        int v = (t >= o) ? partial[t - o] : 0;
        __syncthreads();
        partial[t] += v;
        __syncthreads();
    }
    int run = (t == 0) ? 0 : partial[t - 1];
    for (int i = 0; i < CH; i++) {
        int idx = base + i;
        if (idx < N_NODES) {
            g_off[idx] = run;
            g_cur[idx] = run;
            run += g_cnt[idx];
        }
    }
    if (t == 1023) g_off[N_NODES] = partial[1023];
}

// ---------------------------------------------------------------------------
// K2d: scatter packed edge meta {h2 row offset (floats), norm} into dst bins.
// ---------------------------------------------------------------------------
__global__ __launch_bounds__(256)
void scatter_kernel(const int* __restrict__ src,
                    const int* __restrict__ dst,
                    const int* __restrict__ rel,
                    const float* __restrict__ norm) {
    int e = blockIdx.x * 256 + threadIdx.x;
    if (e >= N_EDGES) return;
    const int is64 = g_src_is64;
    const int s  = is64 ? src[2 * e] : src[e];
    const int d  = dst[e];
    const int rl = rel[e];
    const float nm = norm[e];
    int pos = atomicAdd(&g_cur[d], 1);
    g_meta[pos] = make_int2((s * NUM_RELS + rl) * FEAT, __float_as_int(nm));
}

// ---------------------------------------------------------------------------
// K3: gather-side aggregation, NO float atomics.
// 12 threads per dst (one float4 quad each) sum over the dst's contiguous
// edge list in registers; bias2 + relu fused at writeback.
// 192 threads/block = 16 dsts.
// ---------------------------------------------------------------------------
__global__ __launch_bounds__(192)
void agg_kernel(const float* __restrict__ b2, float* __restrict__ out) {
    const int t = threadIdx.x;
    const int d = blockIdx.x * 16 + t / 12;
    const int q = t % 12;
    if (d >= N_NODES) return;

    int p  = g_off[d];
    const int pe = g_off[d + 1];

    float4 acc = make_float4(0.f, 0.f, 0.f, 0.f);

    // 2-way unrolled for MLP
    for (; p + 1 < pe; p += 2) {
        int2 m0 = g_meta[p];
        int2 m1 = g_meta[p + 1];
        const float4* r0 = reinterpret_cast<const float4*>(g_h2 + (size_t)m0.x);
        const float4* r1 = reinterpret_cast<const float4*>(g_h2 + (size_t)m1.x);
        float4 v0 = r0[q];
        float4 v1 = r1[q];
        float n0 = __int_as_float(m0.y);
        float n1 = __int_as_float(m1.y);
        acc.x = fmaf(v0.x, n0, acc.x);
        acc.y = fmaf(v0.y, n0, acc.y);
        acc.z = fmaf(v0.z, n0, acc.z);
        acc.w = fmaf(v0.w, n0, acc.w);
        acc.x = fmaf(v1.x, n1, acc.x);
        acc.y = fmaf(v1.y, n1, acc.y);
        acc.z = fmaf(v1.z, n1, acc.z);
        acc.w = fmaf(v1.w, n1, acc.w);
    }
    if (p < pe) {
        int2 m0 = g_meta[p];
        const float4* r0 = reinterpret_cast<const float4*>(g_h2 + (size_t)m0.x);
        float4 v0 = r0[q];
        float n0 = __int_as_float(m0.y);
        acc.x = fmaf(v0.x, n0, acc.x);
        acc.y = fmaf(v0.y, n0, acc.y);
        acc.z = fmaf(v0.z, n0, acc.z);
        acc.w = fmaf(v0.w, n0, acc.w);
    }

    float4 bb = reinterpret_cast<const float4*>(b2)[q];
    float4 o;
    o.x = fmaxf(acc.x + bb.x, 0.0f);
    o.y = fmaxf(acc.y + bb.y, 0.0f);
    o.z = fmaxf(acc.z + bb.z, 0.0f);
    o.w = fmaxf(acc.w + bb.w, 0.0f);
    reinterpret_cast<float4*>(out + (size_t)d * FEAT)[q] = o;
}

// ---------------------------------------------------------------------------
// launch
// ---------------------------------------------------------------------------
extern "C" void kernel_launch(void* const* d_in, const int* in_sizes, int n_in,
                              void* d_out, int out_size) {
    const float* X    = (const float*)d_in[0];
    const float* norm = (const float*)d_in[1];
    const float* W1   = (const float*)d_in[2];
    const float* W2   = (const float*)d_in[3];
    const float* b1   = (const float*)d_in[4];
    const float* b2   = (const float*)d_in[5];
    const int*   src  = (const int*)d_in[6];   // int32 or int64 (detected)
    const int*   dst  = (const int*)d_in[7];
    const int*   rel  = (const int*)d_in[8];
    float* out = (float*)d_out;

    (void)in_sizes; (void)n_in; (void)out_size;

    detect_kernel<<<1, 256>>>(src);
    zero_cnt_kernel<<<(N_NODES + 255) / 256, 256>>>();

    // fused dense stage -> g_h2 (2 nodes/thread, 256 nodes/block)
    dim3 g1((N_NODES + 255) / 256, NUM_RELS);
    rgcn_gemm_kernel<<<g1, 128>>>(X, W1, W2, b1);

    // counting-sort edges by dst
    hist_kernel<<<(N_EDGES + 255) / 256, 256>>>(dst);
    scan_kernel<<<1, 1024>>>();
    scatter_kernel<<<(N_EDGES + 255) / 256, 256>>>(src, dst, rel, norm);

    // gather-side aggregation + bias2 + relu (writes every out element)
    agg_kernel<<<(N_NODES + 15) / 16, 192>>>(b2, out);
}

// round 7
// speedup vs baseline: 1.0451x; 1.0451x over previous
#include <cuda_runtime.h>
#include <cuda_bf16.h>
#include <cstdint>

#define N_NODES 50000
#define N_EDGES 1600000
#define FEAT    48
#define NUM_RELS 8

// ---------------------------------------------------------------------------
// Scratch (__device__ globals — no allocations).
// ---------------------------------------------------------------------------
__device__ float g_h2[(size_t)N_NODES * NUM_RELS * FEAT];   // 76.8 MB
__device__ int   g_cnt[N_NODES];
__device__ int   g_off[N_NODES + 1];
__device__ int   g_cur[N_NODES];
__device__ int2  g_meta[N_EDGES];                            // 12.8 MB
__device__ int   g_src_is64;

// ---------------------------------------------------------------------------
// Packed f32x2 helpers (Blackwell) — only reachable via PTX.
// ---------------------------------------------------------------------------
__device__ __forceinline__ unsigned long long pack2(float lo, float hi) {
    unsigned long long r;
    asm("mov.b64 %0, {%1, %2};" : "=l"(r) : "f"(lo), "f"(hi));
    return r;
}
__device__ __forceinline__ void unpack2(float& lo, float& hi, unsigned long long v) {
    asm("mov.b64 {%0, %1}, %2;" : "=f"(lo), "=f"(hi) : "l"(v));
}
#define FMA2(d, a, b) \
    asm("fma.rn.f32x2 %0, %1, %2, %0;" : "+l"(d) : "l"(a), "l"(b))

// ---------------------------------------------------------------------------
// K1 (launch #1): zero counts + src dtype detection (block 0).
// int64 detection: hi words of 256 int64 node ids all zero — impossible for
// random int32 node-id data.
// ---------------------------------------------------------------------------
__global__ void zero_detect_kernel(const int* __restrict__ src) {
    int i = blockIdx.x * 256 + threadIdx.x;
    if (i < N_NODES) g_cnt[i] = 0;
    if (blockIdx.x == 0) {
        __shared__ int s_any;
        if (threadIdx.x == 0) s_any = 0;
        __syncthreads();
        unsigned v = (unsigned)src[2 * threadIdx.x + 1];
        unsigned any = __ballot_sync(0xFFFFFFFFu, v != 0u);
        if ((threadIdx.x & 31) == 0 && any) atomicOr(&s_any, 1);
        __syncthreads();
        if (threadIdx.x == 0) g_src_is64 = (s_any == 0) ? 1 : 0;
    }
}

// ---------------------------------------------------------------------------
// K2 (launch #2): dst histogram, int4-vectorized (4 edges/thread).
// ---------------------------------------------------------------------------
__global__ __launch_bounds__(256)
void hist_kernel(const int4* __restrict__ dst4) {
    int i = blockIdx.x * 256 + threadIdx.x;
    if (i < N_EDGES / 4) {
        int4 d = dst4[i];
        atomicAdd(&g_cnt[d.x], 1);
        atomicAdd(&g_cnt[d.y], 1);
        atomicAdd(&g_cnt[d.z], 1);
        atomicAdd(&g_cnt[d.w], 1);
    }
}

// ---------------------------------------------------------------------------
// K3 (launch #3): single-block exclusive scan g_cnt -> g_off, g_cur.
// ---------------------------------------------------------------------------
__global__ __launch_bounds__(1024)
void scan_kernel() {
    __shared__ int partial[1024];
    const int t = threadIdx.x;
    const int CH = (N_NODES + 1023) / 1024;  // 49
    const int base = t * CH;

    int s = 0;
    for (int i = 0; i < CH; i++) {
        int idx = base + i;
        if (idx < N_NODES) s += g_cnt[idx];
    }
    partial[t] = s;
    __syncthreads();
    for (int o = 1; o < 1024; o <<= 1) {
        int v = (t >= o) ? partial[t - o] : 0;
        __syncthreads();
        partial[t] += v;
        __syncthreads();
    }
    int run = (t == 0) ? 0 : partial[t - 1];
    for (int i = 0; i < CH; i++) {
        int idx = base + i;
        if (idx < N_NODES) {
            g_off[idx] = run;
            g_cur[idx] = run;
            run += g_cnt[idx];
        }
    }
    if (t == 1023) g_off[N_NODES] = partial[1023];
}

// ---------------------------------------------------------------------------
// K4 (launch #4 — THIS is what ncu captures): fused dense stage.
//   h1 = relu(x @ W1[r] + b1); h2 = h1 @ W2[r]  -> g_h2[n][r][:]
// 2 nodes/thread; BOTH stages share weight LDS across the two nodes
// (stage-2 LDS:FMA2 ratio improved 1:1 -> 1:2).
// ---------------------------------------------------------------------------
__global__ __launch_bounds__(128, 2)
void rgcn_gemm_kernel(const float* __restrict__ X,
                      const float* __restrict__ W1,
                      const float* __restrict__ W2,
                      const float* __restrict__ b1) {
    __shared__ __align__(16) float W1s[FEAT * FEAT];
    __shared__ __align__(16) float W2s[FEAT * FEAT];
    __shared__ float b1s[FEAT];

    const int r   = blockIdx.y;
    const int tid = threadIdx.x;

    const float* w1g = W1 + (size_t)r * FEAT * FEAT;
    const float* w2g = W2 + (size_t)r * FEAT * FEAT;
    for (int k = tid; k < FEAT * FEAT; k += 128) {
        W1s[k] = w1g[k];
        W2s[k] = w2g[k];
    }
    if (tid < FEAT) b1s[tid] = b1[tid];
    __syncthreads();

    const int n0 = blockIdx.x * 256 + tid;
    const int n1 = n0 + 128;
    const bool v0 = (n0 < N_NODES);
    const bool v1 = (n1 < N_NODES);
    const int c0 = v0 ? n0 : 0;
    const int c1 = v1 ? n1 : 0;

    // ---- stage 1: h1 = relu(x @ W1 + b1), shared weight loads ----
    unsigned long long accA[FEAT / 2], accB[FEAT / 2];
#pragma unroll
    for (int k = 0; k < FEAT / 2; k++) {
        unsigned long long b = pack2(b1s[2 * k], b1s[2 * k + 1]);
        accA[k] = b;
        accB[k] = b;
    }

    const float4* xa4 = reinterpret_cast<const float4*>(X + (size_t)c0 * FEAT);
    const float4* xb4 = reinterpret_cast<const float4*>(X + (size_t)c1 * FEAT);
#pragma unroll
    for (int i4 = 0; i4 < FEAT / 4; i4++) {
        float4 xa = xa4[i4];
        float4 xb = xb4[i4];
#pragma unroll
        for (int u = 0; u < 4; u++) {
            float ai = (u == 0) ? xa.x : (u == 1) ? xa.y : (u == 2) ? xa.z : xa.w;
            float bi = (u == 0) ? xb.x : (u == 1) ? xb.y : (u == 2) ? xb.z : xb.w;
            unsigned long long a2 = pack2(ai, ai);
            unsigned long long b2 = pack2(bi, bi);
            const ulonglong2* w =
                reinterpret_cast<const ulonglong2*>(W1s + (i4 * 4 + u) * FEAT);
#pragma unroll
            for (int k = 0; k < FEAT / 4; k++) {
                ulonglong2 wv = w[k];
                FMA2(accA[2 * k],     a2, wv.x);
                FMA2(accA[2 * k + 1], a2, wv.y);
                FMA2(accB[2 * k],     b2, wv.x);
                FMA2(accB[2 * k + 1], b2, wv.y);
            }
        }
    }

    float hA[FEAT], hB[FEAT];
#pragma unroll
    for (int k = 0; k < FEAT / 2; k++) {
        float lo, hi;
        unpack2(lo, hi, accA[k]);
        hA[2 * k]     = fmaxf(lo, 0.0f);
        hA[2 * k + 1] = fmaxf(hi, 0.0f);
        unpack2(lo, hi, accB[k]);
        hB[2 * k]     = fmaxf(lo, 0.0f);
        hB[2 * k + 1] = fmaxf(hi, 0.0f);
    }

    // ---- stage 2: h2 = h1 @ W2, weight loads shared across both nodes ----
    unsigned long long acc2A[FEAT / 2], acc2B[FEAT / 2];
#pragma unroll
    for (int k = 0; k < FEAT / 2; k++) { acc2A[k] = 0ull; acc2B[k] = 0ull; }

#pragma unroll
    for (int j = 0; j < FEAT; j++) {
        unsigned long long hjA = pack2(hA[j], hA[j]);
        unsigned long long hjB = pack2(hB[j], hB[j]);
        const ulonglong2* w = reinterpret_cast<const ulonglong2*>(W2s + j * FEAT);
#pragma unroll
        for (int k = 0; k < FEAT / 4; k++) {
            ulonglong2 wv = w[k];
            FMA2(acc2A[2 * k],     hjA, wv.x);
            FMA2(acc2A[2 * k + 1], hjA, wv.y);
            FMA2(acc2B[2 * k],     hjB, wv.x);
            FMA2(acc2B[2 * k + 1], hjB, wv.y);
        }
    }

    if (v0) {
        ulonglong2* orow = reinterpret_cast<ulonglong2*>(
            g_h2 + ((size_t)n0 * NUM_RELS + r) * FEAT);
#pragma unroll
        for (int k = 0; k < FEAT / 4; k++) {
            ulonglong2 o; o.x = acc2A[2 * k]; o.y = acc2A[2 * k + 1];
            orow[k] = o;
        }
    }
    if (v1) {
        ulonglong2* orow = reinterpret_cast<ulonglong2*>(
            g_h2 + ((size_t)n1 * NUM_RELS + r) * FEAT);
#pragma unroll
        for (int k = 0; k < FEAT / 4; k++) {
            ulonglong2 o; o.x = acc2B[2 * k]; o.y = acc2B[2 * k + 1];
            orow[k] = o;
        }
    }
}

// ---------------------------------------------------------------------------
// K5 (launch #5): scatter packed {h2 row offset, norm} into dst bins.
// ---------------------------------------------------------------------------
__global__ __launch_bounds__(256)
void scatter_kernel(const int* __restrict__ src,
                    const int* __restrict__ dst,
                    const int* __restrict__ rel,
                    const float* __restrict__ norm) {
    int e = blockIdx.x * 256 + threadIdx.x;
    if (e >= N_EDGES) return;
    const int is64 = g_src_is64;
    const int s  = is64 ? src[2 * e] : src[e];
    const int d  = dst[e];
    const int rl = rel[e];
    const float nm = norm[e];
    int pos = atomicAdd(&g_cur[d], 1);
    g_meta[pos] = make_int2((s * NUM_RELS + rl) * FEAT, __float_as_int(nm));
}

// ---------------------------------------------------------------------------
// K6 (launch #6): gather-side aggregation, no float atomics.
// 12 threads per dst (one float4 quad each); 4-way unrolled for MLP≈4;
// bias2 + relu fused at writeback. 192 threads/block = 16 dsts.
// ---------------------------------------------------------------------------
__global__ __launch_bounds__(192)
void agg_kernel(const float* __restrict__ b2, float* __restrict__ out) {
    const int t = threadIdx.x;
    const int d = blockIdx.x * 16 + t / 12;
    const int q = t % 12;
    if (d >= N_NODES) return;

    const int2*  __restrict__ meta = g_meta;
    const float* __restrict__ h2   = g_h2;

    int p  = g_off[d];
    const int pe = g_off[d + 1];

    float4 acc = make_float4(0.f, 0.f, 0.f, 0.f);

    for (; p + 3 < pe; p += 4) {
        int2 m0 = meta[p];
        int2 m1 = meta[p + 1];
        int2 m2 = meta[p + 2];
        int2 m3 = meta[p + 3];
        float4 v0 = reinterpret_cast<const float4*>(h2 + (size_t)m0.x)[q];
        float4 v1 = reinterpret_cast<const float4*>(h2 + (size_t)m1.x)[q];
        float4 v2 = reinterpret_cast<const float4*>(h2 + (size_t)m2.x)[q];
        float4 v3 = reinterpret_cast<const float4*>(h2 + (size_t)m3.x)[q];
        float n0 = __int_as_float(m0.y);
        float n1 = __int_as_float(m1.y);
        float n2 = __int_as_float(m2.y);
        float n3 = __int_as_float(m3.y);
        acc.x = fmaf(v0.x, n0, acc.x); acc.y = fmaf(v0.y, n0, acc.y);
        acc.z = fmaf(v0.z, n0, acc.z); acc.w = fmaf(v0.w, n0, acc.w);
        acc.x = fmaf(v1.x, n1, acc.x); acc.y = fmaf(v1.y, n1, acc.y);
        acc.z = fmaf(v1.z, n1, acc.z); acc.w = fmaf(v1.w, n1, acc.w);
        acc.x = fmaf(v2.x, n2, acc.x); acc.y = fmaf(v2.y, n2, acc.y);
        acc.z = fmaf(v2.z, n2, acc.z); acc.w = fmaf(v2.w, n2, acc.w);
        acc.x = fmaf(v3.x, n3, acc.x); acc.y = fmaf(v3.y, n3, acc.y);
        acc.z = fmaf(v3.z, n3, acc.z); acc.w = fmaf(v3.w, n3, acc.w);
    }
    for (; p < pe; p++) {
        int2 m0 = meta[p];
        float4 v0 = reinterpret_cast<const float4*>(h2 + (size_t)m0.x)[q];
        float n0 = __int_as_float(m0.y);
        acc.x = fmaf(v0.x, n0, acc.x); acc.y = fmaf(v0.y, n0, acc.y);
        acc.z = fmaf(v0.z, n0, acc.z); acc.w = fmaf(v0.w, n0, acc.w);
    }

    float4 bb = reinterpret_cast<const float4*>(b2)[q];
    float4 o;
    o.x = fmaxf(acc.x + bb.x, 0.0f);
    o.y = fmaxf(acc.y + bb.y, 0.0f);
    o.z = fmaxf(acc.z + bb.z, 0.0f);
    o.w = fmaxf(acc.w + bb.w, 0.0f);
    reinterpret_cast<float4*>(out + (size_t)d * FEAT)[q] = o;
}

// ---------------------------------------------------------------------------
// launch — ORDER MATTERS: gemm is the 4th launch so ncu captures it.
// ---------------------------------------------------------------------------
extern "C" void kernel_launch(void* const* d_in, const int* in_sizes, int n_in,
                              void* d_out, int out_size) {
    const float* X    = (const float*)d_in[0];
    const float* norm = (const float*)d_in[1];
    const float* W1   = (const float*)d_in[2];
    const float* W2   = (const float*)d_in[3];
    const float* b1   = (const float*)d_in[4];
    const float* b2   = (const float*)d_in[5];
    const int*   src  = (const int*)d_in[6];   // int32 or int64 (detected)
    const int*   dst  = (const int*)d_in[7];
    const int*   rel  = (const int*)d_in[8];
    float* out = (float*)d_out;

    (void)in_sizes; (void)n_in; (void)out_size;

    // #1: zero counts + dtype detect
    zero_detect_kernel<<<(N_NODES + 255) / 256, 256>>>(src);
    // #2: dst histogram
    hist_kernel<<<(N_EDGES / 4 + 255) / 256, 256>>>((const int4*)dst);
    // #3: prefix scan
    scan_kernel<<<1, 1024>>>();
    // #4: fused dense stage (PROFILED)
    dim3 g1((N_NODES + 255) / 256, NUM_RELS);
    rgcn_gemm_kernel<<<g1, 128>>>(X, W1, W2, b1);
    // #5: bin edges by dst
    scatter_kernel<<<(N_EDGES + 255) / 256, 256>>>(src, dst, rel, norm);
    // #6: gather aggregation + bias + relu
    agg_kernel<<<(N_NODES + 15) / 16, 192>>>(b2, out);
}